// round 9
// baseline (speedup 1.0000x reference)
#include <cuda_runtime.h>
#include <cuda_bf16.h>
#include <stdint.h>

#define CIN    16
#define COUT   32
#define KK     27
#define TPB    256
#define HBLK   512                        // 4 pairs x 128 h
#define PROWS  128                        // rows per pair tile
#define PLANE  520                        // words per quad-plane (128*4 + 8 pad)
#define PTILE  (4 * PLANE)                // 2080 words per pair
#define MAX_H  300576
#define MAX_B  1024

__device__ float g_xt[(size_t)MAX_H * CIN];   // transposed x: [h][c]; row H = zeros
__device__ int   g_nk[(size_t)KK * MAX_H];    // clamped indices, [k][h]
__device__ float g_psum[MAX_B * COUT];
__device__ float g_psq [MAX_B * COUT];
__device__ float g_scale[COUT];
__device__ float g_shift[COUT];
__device__ int   g_is64;

typedef unsigned long long ull;

__device__ __forceinline__ void fma2(ull& d, ull a, ull b) {
    asm("fma.rn.f32x2 %0, %1, %2, %0;" : "+l"(d) : "l"(a), "l"(b));
}
__device__ __forceinline__ ull pack2(float v) {
    float2 t = make_float2(v, v);
    return *reinterpret_cast<ull*>(&t);
}
__device__ __forceinline__ void cp16(uint32_t dst_smem, const void* src) {
    asm volatile("cp.async.cg.shared.global [%0], [%1], 16;"
                 :: "r"(dst_smem), "l"(src));
}

// ---------------------------------------------------------------------------
__global__ void detect_kernel(const long long* __restrict__ neigh,
                              int H, long long n_elems) {
    __shared__ int bad;
    if (threadIdx.x == 0) bad = 0;
    __syncthreads();
    long long n64 = n_elems / 2;
    long long lim = n64 < 4096 ? n64 : 4096;
    for (long long i = threadIdx.x; i < lim; i += blockDim.x) {
        long long v = neigh[i];
        if (v < -1 || v >= (long long)H) bad = 1;
    }
    __syncthreads();
    if (threadIdx.x == 0) g_is64 = (bad == 0);
}

// ---------------------------------------------------------------------------
__global__ void prep_kernel(const void* __restrict__ neigh_raw, int H, int Hcover) {
    int h = blockIdx.x * blockDim.x + threadIdx.x;
    if (h >= Hcover) return;
    if (h >= H) {
#pragma unroll
        for (int k = 0; k < KK; k++) g_nk[(size_t)k * MAX_H + h] = H;
        return;
    }
    if (g_is64) {
        const long long* nrow = (const long long*)neigh_raw + (long long)h * KK;
#pragma unroll
        for (int k = 0; k < KK; k++) {
            long long v = nrow[k];
            g_nk[(size_t)k * MAX_H + h] = (v < 0 || v >= (long long)H) ? H : (int)v;
        }
    } else {
        const int* nrow = (const int*)neigh_raw + (long long)h * KK;
#pragma unroll
        for (int k = 0; k < KK; k++) {
            int v = nrow[k];
            g_nk[(size_t)k * MAX_H + h] = ((unsigned)v >= (unsigned)H) ? H : v;
        }
    }
}

// ---------------------------------------------------------------------------
__global__ void transpose_kernel(const float* __restrict__ x, int H) {
    int h = blockIdx.x * blockDim.x + threadIdx.x;
    float4* dst = reinterpret_cast<float4*>(&g_xt[(size_t)h * CIN]);
    if (h < H) {
        float v[CIN];
#pragma unroll
        for (int c = 0; c < CIN; c++) v[c] = x[(size_t)c * H + h];
#pragma unroll
        for (int j = 0; j < CIN / 4; j++)
            dst[j] = make_float4(v[4 * j], v[4 * j + 1], v[4 * j + 2], v[4 * j + 3]);
    } else if (h < H + 32 && h < MAX_H) {
        float4 z = make_float4(0.f, 0.f, 0.f, 0.f);
#pragma unroll
        for (int j = 0; j < CIN / 4; j++) dst[j] = z;
    }
}

// ---------------------------------------------------------------------------
// Gather-conv: 4 independent warp-pairs per block.
//   Pair p shares a 128-row gathered x tile (cp.async staged, split between
//   its 2 warps). Warp og=0 computes o[0,16), og=1 o[16,32); each thread 4 h.
//   Pair-scope sync via named barriers -> pairs pipeline independently.
// Weights [k][i][o] in smem; one 16B broadcast LDS feeds 8 fma2 (2op x 4h).
// ---------------------------------------------------------------------------
__global__ __launch_bounds__(TPB, 2)
void conv_kernel(const float* __restrict__ w,
                 float* __restrict__ out, int H) {
    extern __shared__ float smem[];
    float* ws = smem;                                 // 13824 floats
    float* xtiles = smem + KK * CIN * COUT;           // 4 * PTILE floats
    __shared__ float s_sum[TPB / 32][16];
    __shared__ float s_sq [TPB / 32][16];

    // ws[(k*CIN+i)*COUT + o] = w[(o*CIN+i)*KK + k]
    for (int idx = threadIdx.x; idx < KK * COUT * CIN; idx += TPB) {
        int k = idx / (CIN * COUT);
        int r = idx - k * (CIN * COUT);
        int i = r >> 5;
        int o = r & 31;
        ws[idx] = w[(o * CIN + i) * KK + k];
    }
    __syncthreads();

    int lane = threadIdx.x & 31;
    int warp = threadIdx.x >> 5;
    int pair = warp >> 1;                   // 0..3
    int og   = warp & 1;                    // o-group
    int obase = og * 16;
    int pl   = (og << 5) | lane;            // pair-local thread 0..63
    int bar  = pair + 1;                    // named barrier id

    float* xt = xtiles + pair * PTILE;
    int hbase = blockIdx.x * HBLK + pair * PROWS;
    const int* nkp = g_nk + hbase;

    ull acc[4][8];                          // [rr][opair]
#pragma unroll
    for (int rr = 0; rr < 4; rr++)
#pragma unroll
        for (int m = 0; m < 8; m++) acc[rr][m] = 0ULL;

#pragma unroll 1
    for (int k = 0; k < KK; k++) {
        // ---- stage 128 rows (512 x 16B chunks, 8 per thread) ----
        const int* nk = nkp + (size_t)k * MAX_H;
#pragma unroll
        for (int t = 0; t < 8; t++) {
            int c = t * 64 + pl;            // 0..511
            int row = c >> 2, q = c & 3;
            int n = nk[row];
            uint32_t dst = (uint32_t)__cvta_generic_to_shared(
                &xt[q * PLANE + row * 4]);
            cp16(dst, &g_xt[(size_t)n * CIN + q * 4]);
        }
        asm volatile("cp.async.commit_group;");
        asm volatile("cp.async.wait_group 0;" ::: "memory");
        asm volatile("bar.sync %0, 64;" :: "r"(bar) : "memory");

        // ---- compute: 4 rows (lane, lane+32, lane+64, lane+96), 16 o ----
#pragma unroll
        for (int q = 0; q < 4; q++) {
            float4 v[4];
#pragma unroll
            for (int rr = 0; rr < 4; rr++)
                v[rr] = *reinterpret_cast<const float4*>(
                    &xt[q * PLANE + (rr * 32 + lane) * 4]);
#pragma unroll
            for (int e = 0; e < 4; e++) {
                int i = q * 4 + e;
                ull xa[4];
                xa[0] = pack2(e == 0 ? v[0].x : e == 1 ? v[0].y : e == 2 ? v[0].z : v[0].w);
                xa[1] = pack2(e == 0 ? v[1].x : e == 1 ? v[1].y : e == 2 ? v[1].z : v[1].w);
                xa[2] = pack2(e == 0 ? v[2].x : e == 1 ? v[2].y : e == 2 ? v[2].z : v[2].w);
                xa[3] = pack2(e == 0 ? v[3].x : e == 1 ? v[3].y : e == 2 ? v[3].z : v[3].w);
                const ulonglong2* wr = reinterpret_cast<const ulonglong2*>(
                    &ws[(k * CIN + i) * COUT + obase]);
#pragma unroll
                for (int m = 0; m < 4; m++) {
                    ulonglong2 wv = wr[m];            // broadcast LDS.128
#pragma unroll
                    for (int rr = 0; rr < 4; rr++) {
                        fma2(acc[rr][2 * m],     xa[rr], wv.x);
                        fma2(acc[rr][2 * m + 1], xa[rr], wv.y);
                    }
                }
            }
        }
        asm volatile("bar.sync %0, 64;" :: "r"(bar) : "memory");  // tile reuse
    }

    // unpack accumulators -> y[rr][16]
    float y[4][16];
#pragma unroll
    for (int rr = 0; rr < 4; rr++)
#pragma unroll
        for (int m = 0; m < 8; m++) {
            float2 p = *reinterpret_cast<float2*>(&acc[rr][m]);
            y[rr][2 * m] = p.x;
            y[rr][2 * m + 1] = p.y;
        }

#pragma unroll
    for (int rr = 0; rr < 4; rr++) {
        int h = hbase + rr * 32 + lane;
        if (h < H) {
#pragma unroll
            for (int o = 0; o < 16; o++)
                out[(size_t)(obase + o) * H + h] = y[rr][o];
        }
    }

    // --- deterministic block reduction (padded h give exact 0) ---
#pragma unroll
    for (int o = 0; o < 16; o++) {
        float v  = ((y[0][o] + y[1][o]) + y[2][o]) + y[3][o];
        float v2 = ((y[0][o] * y[0][o] + y[1][o] * y[1][o]) +
                     y[2][o] * y[2][o]) + y[3][o] * y[3][o];
#pragma unroll
        for (int off = 16; off > 0; off >>= 1) {
            v  += __shfl_xor_sync(0xFFFFFFFFu, v,  off);
            v2 += __shfl_xor_sync(0xFFFFFFFFu, v2, off);
        }
        if (lane == 0) { s_sum[warp][o] = v; s_sq[warp][o] = v2; }
    }
    __syncthreads();
    if (threadIdx.x < COUT) {
        int o = threadIdx.x;
        int wstart = (o < 16) ? 0 : 1;      // og matching this o
        int oc = o & 15;
        float S = 0.0f, Q = 0.0f;
#pragma unroll
        for (int p = 0; p < 4; p++) {
            S += s_sum[2 * p + wstart][oc];
            Q += s_sq [2 * p + wstart][oc];
        }
        g_psum[(size_t)blockIdx.x * COUT + o] = S;
        g_psq [(size_t)blockIdx.x * COUT + o] = Q;
    }
}

// ---------------------------------------------------------------------------
__global__ void stats_kernel(const float* __restrict__ gamma,
                             const float* __restrict__ beta,
                             int H, int NB) {
    int o = blockIdx.x;
    float S = 0.0f, Q = 0.0f;
    for (int b = threadIdx.x; b < NB; b += blockDim.x) {
        S += g_psum[(size_t)b * COUT + o];
        Q += g_psq [(size_t)b * COUT + o];
    }
    __shared__ float ss[256], sq[256];
    ss[threadIdx.x] = S;
    sq[threadIdx.x] = Q;
    __syncthreads();
    for (int off = 128; off > 0; off >>= 1) {
        if (threadIdx.x < off) {
            ss[threadIdx.x] += ss[threadIdx.x + off];
            sq[threadIdx.x] += sq[threadIdx.x + off];
        }
        __syncthreads();
    }
    if (threadIdx.x == 0) {
        float invH = 1.0f / (float)H;
        float mean = ss[0] * invH;
        float var  = sq[0] * invH - mean * mean;
        float sc   = gamma[o] * rsqrtf(var + 1e-5f);
        g_scale[o] = sc;
        g_shift[o] = beta[o] - mean * sc;
    }
}

// ---------------------------------------------------------------------------
__global__ void norm_kernel(float* __restrict__ out, int H) {
    int o = blockIdx.y;
    int i = blockIdx.x * blockDim.x + threadIdx.x;
    int H4 = H >> 2;
    float sc = g_scale[o], sh = g_shift[o];
    float4* p = reinterpret_cast<float4*>(out + (size_t)o * H);
    if (i < H4) {
        float4 v = p[i];
        v.x = v.x * sc + sh;
        v.y = v.y * sc + sh;
        v.z = v.z * sc + sh;
        v.w = v.w * sc + sh;
        p[i] = v;
    }
    if (blockIdx.x == 0 && threadIdx.x < (H & 3)) {
        int hh = H4 * 4 + threadIdx.x;
        out[(size_t)o * H + hh] = out[(size_t)o * H + hh] * sc + sh;
    }
}

// ---------------------------------------------------------------------------
extern "C" void kernel_launch(void* const* d_in, const int* in_sizes, int n_in,
                              void* d_out, int out_size) {
    const float* x     = (const float*)d_in[0];
    const float* w     = (const float*)d_in[1];
    const float* gamma = (const float*)d_in[2];
    const float* beta  = (const float*)d_in[3];
    const void*  neigh = d_in[4];

    int H  = in_sizes[0] / CIN;
    int NB = (H + HBLK - 1) / HBLK;
    int Hcover = NB * HBLK;
    long long n_neigh = (long long)in_sizes[4];

    static const int kSmemBytes =
        (KK * COUT * CIN + 4 * PTILE) * (int)sizeof(float);   // 88576
    cudaFuncSetAttribute(conv_kernel,
                         cudaFuncAttributeMaxDynamicSharedMemorySize, kSmemBytes);

    detect_kernel<<<1, 256>>>((const long long*)neigh, H, n_neigh);
    prep_kernel<<<(Hcover + 255) / 256, 256>>>(neigh, H, Hcover);
    transpose_kernel<<<(H + 32 + 255) / 256, 256>>>(x, H);
    conv_kernel<<<NB, TPB, kSmemBytes>>>(w, (float*)d_out, H);
    stats_kernel<<<COUT, 256>>>(gamma, beta, H, NB);
    dim3 ngrid((H / 4 + 255) / 256, COUT);
    norm_kernel<<<ngrid, 256>>>((float*)d_out, H);
}

// round 11
// speedup vs baseline: 1.3864x; 1.3864x over previous
#include <cuda_runtime.h>
#include <cuda_bf16.h>
#include <stdint.h>

#define CIN    16
#define COUT   32
#define KK     27
#define TPB    256
#define HBLK   512                        // 8 warps x 64 h
#define ROWSTR 20                         // tile row stride in words (80B, bank-clean)
#define TILEW  (64 * ROWSTR)              // 1280 words per buffer
#define MAX_H  300064
#define MAX_B  1024

__device__ float g_xt[(size_t)MAX_H * CIN];   // transposed x: [h][c]; row H = zeros
__device__ int   g_nk[(size_t)KK * MAX_H];    // clamped indices, [k][h]
__device__ float g_ws[KK * CIN * COUT];       // weights reordered [k][i][o]
__device__ float g_psum[MAX_B * COUT];
__device__ float g_psq [MAX_B * COUT];
__device__ float g_scale[COUT];
__device__ float g_shift[COUT];
__device__ int   g_is64;

typedef unsigned long long ull;

__device__ __forceinline__ void fma2(ull& d, ull a, ull b) {
    asm("fma.rn.f32x2 %0, %1, %2, %0;" : "+l"(d) : "l"(a), "l"(b));
}
__device__ __forceinline__ ull pack2(float v) {
    float2 t = make_float2(v, v);
    return *reinterpret_cast<ull*>(&t);
}
__device__ __forceinline__ void cp16(uint32_t dst_smem, const void* src) {
    asm volatile("cp.async.cg.shared.global [%0], [%1], 16;"
                 :: "r"(dst_smem), "l"(src));
}

// ---------------------------------------------------------------------------
__global__ void detect_kernel(const long long* __restrict__ neigh,
                              int H, long long n_elems) {
    __shared__ int bad;
    if (threadIdx.x == 0) bad = 0;
    __syncthreads();
    long long n64 = n_elems / 2;
    long long lim = n64 < 4096 ? n64 : 4096;
    for (long long i = threadIdx.x; i < lim; i += blockDim.x) {
        long long v = neigh[i];
        if (v < -1 || v >= (long long)H) bad = 1;
    }
    __syncthreads();
    if (threadIdx.x == 0) g_is64 = (bad == 0);
}

// ---------------------------------------------------------------------------
__global__ void prep_kernel(const void* __restrict__ neigh_raw, int H, int Hcover) {
    int h = blockIdx.x * blockDim.x + threadIdx.x;
    if (h >= Hcover) return;
    if (h >= H) {
#pragma unroll
        for (int k = 0; k < KK; k++) g_nk[(size_t)k * MAX_H + h] = H;
        return;
    }
    if (g_is64) {
        const long long* nrow = (const long long*)neigh_raw + (long long)h * KK;
#pragma unroll
        for (int k = 0; k < KK; k++) {
            long long v = nrow[k];
            g_nk[(size_t)k * MAX_H + h] = (v < 0 || v >= (long long)H) ? H : (int)v;
        }
    } else {
        const int* nrow = (const int*)neigh_raw + (long long)h * KK;
#pragma unroll
        for (int k = 0; k < KK; k++) {
            int v = nrow[k];
            g_nk[(size_t)k * MAX_H + h] = ((unsigned)v >= (unsigned)H) ? H : v;
        }
    }
}

// ---------------------------------------------------------------------------
__global__ void wreorder_kernel(const float* __restrict__ w) {
    int idx = blockIdx.x * blockDim.x + threadIdx.x;
    if (idx >= KK * CIN * COUT) return;
    int k = idx / (CIN * COUT);
    int r = idx - k * (CIN * COUT);
    int i = r >> 5;
    int o = r & 31;
    g_ws[idx] = w[(o * CIN + i) * KK + k];
}

// ---------------------------------------------------------------------------
__global__ void transpose_kernel(const float* __restrict__ x, int H) {
    int h = blockIdx.x * blockDim.x + threadIdx.x;
    float4* dst = reinterpret_cast<float4*>(&g_xt[(size_t)h * CIN]);
    if (h < H) {
        float v[CIN];
#pragma unroll
        for (int c = 0; c < CIN; c++) v[c] = x[(size_t)c * H + h];
#pragma unroll
        for (int j = 0; j < CIN / 4; j++)
            dst[j] = make_float4(v[4 * j], v[4 * j + 1], v[4 * j + 2], v[4 * j + 3]);
    } else if (h < H + 32 && h < MAX_H) {
        float4 z = make_float4(0.f, 0.f, 0.f, 0.f);
#pragma unroll
        for (int j = 0; j < CIN / 4; j++) dst[j] = z;
    }
}

// ---------------------------------------------------------------------------
// Gather-conv: warp-private double-buffered x tiles via cp.async.
//   Each warp owns 64 h. While computing k from buf[k&1], the gather for
//   k+1 streams into buf[(k+1)&1] (wait_group 1 -> previous group already
//   landed, no exposed latency). Only __syncwarp, no block barriers.
// Weights read via broadcast LDG.128 from g_ws[k][i][o] (L1-resident:
// smem=80KB/block, 2 blocks/SM -> 68KB L1D carveout >= 55KB weights;
// cp.async.cg bypasses L1 so gathers don't evict them).
// Accs: 16 u64 (2 h x 32 o as f32x2 pairs over o).
// ---------------------------------------------------------------------------
__global__ __launch_bounds__(TPB, 2)
void conv_kernel(float* __restrict__ out, int H) {
    extern __shared__ float smem[];                   // 8 warps * 2 * TILEW
    __shared__ float s_sum[TPB / 32][COUT];
    __shared__ float s_sq [TPB / 32][COUT];

    int lane = threadIdx.x & 31;
    int warp = threadIdx.x >> 5;
    float* buf0 = smem + warp * (2 * TILEW);
    float* buf1 = buf0 + TILEW;

    int warpbase = blockIdx.x * HBLK + warp * 64;
    int r0 = lane, r1 = lane + 32;
    int h0 = warpbase + r0, h1 = warpbase + r1;

    int q    = lane & 3;                   // chunk this lane fetches
    int rsub = lane >> 2;                  // row-within-8

    const int* nkw = g_nk + warpbase;

    // stage 64 rows of k into buf (8 cp16 per thread)
    auto stage = [&](int k, float* buf) {
        const int* nk = nkw + (size_t)k * MAX_H;
#pragma unroll
        for (int t = 0; t < 8; t++) {
            int row = t * 8 + rsub;
            int n = nk[row];
            uint32_t dst = (uint32_t)__cvta_generic_to_shared(
                &buf[row * ROWSTR + q * 4]);
            cp16(dst, &g_xt[(size_t)n * CIN + q * 4]);
        }
        asm volatile("cp.async.commit_group;");
    };

    ull acc_a[16], acc_b[16];
#pragma unroll
    for (int m = 0; m < 16; m++) { acc_a[m] = 0ULL; acc_b[m] = 0ULL; }

    stage(0, buf0);

    const ulonglong2* gw = reinterpret_cast<const ulonglong2*>(g_ws);

#pragma unroll 1
    for (int k = 0; k < KK; k++) {
        float* cur = (k & 1) ? buf1 : buf0;
        if (k + 1 < KK) {
            stage(k + 1, (k & 1) ? buf0 : buf1);
            asm volatile("cp.async.wait_group 1;" ::: "memory");
        } else {
            asm volatile("cp.async.wait_group 0;" ::: "memory");
        }
        __syncwarp();

#pragma unroll
        for (int qq = 0; qq < 4; qq++) {
            float4 va = *reinterpret_cast<const float4*>(&cur[r0 * ROWSTR + qq * 4]);
            float4 vb = *reinterpret_cast<const float4*>(&cur[r1 * ROWSTR + qq * 4]);
            float fa[4] = {va.x, va.y, va.z, va.w};
            float fb[4] = {vb.x, vb.y, vb.z, vb.w};
#pragma unroll
            for (int e = 0; e < 4; e++) {
                int i = qq * 4 + e;
                ull xa = pack2(fa[e]);
                ull xb = pack2(fb[e]);
                const ulonglong2* wr = gw + (size_t)(k * CIN + i) * 8;
#pragma unroll
                for (int m = 0; m < 8; m++) {
                    ulonglong2 wv = __ldg(&wr[m]);    // broadcast LDG.128, L1 hit
                    fma2(acc_a[2 * m],     xa, wv.x);
                    fma2(acc_a[2 * m + 1], xa, wv.y);
                    fma2(acc_b[2 * m],     xb, wv.x);
                    fma2(acc_b[2 * m + 1], xb, wv.y);
                }
            }
        }
        __syncwarp();                                 // all reads done before rewrite
    }

    float ya[COUT], yb[COUT];
#pragma unroll
    for (int m = 0; m < 16; m++) {
        float2 pa = *reinterpret_cast<float2*>(&acc_a[m]);
        float2 pb = *reinterpret_cast<float2*>(&acc_b[m]);
        ya[2 * m] = pa.x; ya[2 * m + 1] = pa.y;
        yb[2 * m] = pb.x; yb[2 * m + 1] = pb.y;
    }

    if (h0 < H) {
#pragma unroll
        for (int o = 0; o < COUT; o++) out[(size_t)o * H + h0] = ya[o];
    }
    if (h1 < H) {
#pragma unroll
        for (int o = 0; o < COUT; o++) out[(size_t)o * H + h1] = yb[o];
    }

    // --- deterministic block reduction (padded h rows are exact 0) ---
#pragma unroll
    for (int o = 0; o < COUT; o++) {
        float v  = ya[o] + yb[o];
        float v2 = ya[o] * ya[o] + yb[o] * yb[o];
#pragma unroll
        for (int off = 16; off > 0; off >>= 1) {
            v  += __shfl_xor_sync(0xFFFFFFFFu, v,  off);
            v2 += __shfl_xor_sync(0xFFFFFFFFu, v2, off);
        }
        if (lane == 0) { s_sum[warp][o] = v; s_sq[warp][o] = v2; }
    }
    __syncthreads();
    if (threadIdx.x < COUT) {
        float S = 0.0f, Q = 0.0f;
#pragma unroll
        for (int wdx = 0; wdx < TPB / 32; wdx++) {
            S += s_sum[wdx][threadIdx.x];
            Q += s_sq [wdx][threadIdx.x];
        }
        g_psum[(size_t)blockIdx.x * COUT + threadIdx.x] = S;
        g_psq [(size_t)blockIdx.x * COUT + threadIdx.x] = Q;
    }
}

// ---------------------------------------------------------------------------
__global__ void stats_kernel(const float* __restrict__ gamma,
                             const float* __restrict__ beta,
                             int H, int NB) {
    int o = blockIdx.x;
    float S = 0.0f, Q = 0.0f;
    for (int b = threadIdx.x; b < NB; b += blockDim.x) {
        S += g_psum[(size_t)b * COUT + o];
        Q += g_psq [(size_t)b * COUT + o];
    }
    __shared__ float ss[256], sq[256];
    ss[threadIdx.x] = S;
    sq[threadIdx.x] = Q;
    __syncthreads();
    for (int off = 128; off > 0; off >>= 1) {
        if (threadIdx.x < off) {
            ss[threadIdx.x] += ss[threadIdx.x + off];
            sq[threadIdx.x] += sq[threadIdx.x + off];
        }
        __syncthreads();
    }
    if (threadIdx.x == 0) {
        float invH = 1.0f / (float)H;
        float mean = ss[0] * invH;
        float var  = sq[0] * invH - mean * mean;
        float sc   = gamma[o] * rsqrtf(var + 1e-5f);
        g_scale[o] = sc;
        g_shift[o] = beta[o] - mean * sc;
    }
}

// ---------------------------------------------------------------------------
__global__ void norm_kernel(float* __restrict__ out, int H) {
    int o = blockIdx.y;
    int i = blockIdx.x * blockDim.x + threadIdx.x;
    int H4 = H >> 2;
    float sc = g_scale[o], sh = g_shift[o];
    float4* p = reinterpret_cast<float4*>(out + (size_t)o * H);
    if (i < H4) {
        float4 v = p[i];
        v.x = v.x * sc + sh;
        v.y = v.y * sc + sh;
        v.z = v.z * sc + sh;
        v.w = v.w * sc + sh;
        p[i] = v;
    }
    if (blockIdx.x == 0 && threadIdx.x < (H & 3)) {
        int hh = H4 * 4 + threadIdx.x;
        out[(size_t)o * H + hh] = out[(size_t)o * H + hh] * sc + sh;
    }
}

// ---------------------------------------------------------------------------
extern "C" void kernel_launch(void* const* d_in, const int* in_sizes, int n_in,
                              void* d_out, int out_size) {
    const float* x     = (const float*)d_in[0];
    const float* w     = (const float*)d_in[1];
    const float* gamma = (const float*)d_in[2];
    const float* beta  = (const float*)d_in[3];
    const void*  neigh = d_in[4];

    int H  = in_sizes[0] / CIN;
    int NB = (H + HBLK - 1) / HBLK;
    int Hcover = NB * HBLK;
    long long n_neigh = (long long)in_sizes[4];

    static const int kSmemBytes = 8 * 2 * TILEW * (int)sizeof(float);   // 81920
    cudaFuncSetAttribute(conv_kernel,
                         cudaFuncAttributeMaxDynamicSharedMemorySize, kSmemBytes);

    detect_kernel<<<1, 256>>>((const long long*)neigh, H, n_neigh);
    prep_kernel<<<(Hcover + 255) / 256, 256>>>(neigh, H, Hcover);
    wreorder_kernel<<<(KK * CIN * COUT + 255) / 256, 256>>>(w);
    transpose_kernel<<<(H + 32 + 255) / 256, 256>>>(x, H);
    conv_kernel<<<NB, TPB, kSmemBytes>>>((float*)d_out, H);
    stats_kernel<<<COUT, 256>>>(gamma, beta, H, NB);
    dim3 ngrid((H / 4 + 255) / 256, COUT);
    norm_kernel<<<ngrid, 256>>>((float*)d_out, H);
}